// round 6
// baseline (speedup 1.0000x reference)
#include <cuda_runtime.h>
#include <cuda_bf16.h>

// 2D Haar DWT, single level — persistent single-wave version.
// Input  x  : (B=16, C=64, H=256, W=256) fp32
// Output out: (B, C*4, H/2=128, W/2=128) fp32, planes ordered [cA, cH, cV, cD]
//
// One WARP per (bc, h) input row-pair, grid-stride over row-pairs so the grid
// is exactly one wave (608 CTAs = 152 SMs x 4). Thread `lane` loads float4s at
// row0[lane], row0[lane+32], row1[lane], row1[lane+32] -- every LDG.128 is a
// dense 512B warp transaction. Stores are dense 256B STG.64 transactions into
// each of the 4 output planes. Next iteration's loads overlap this
// iteration's stores (no dependency), giving cross-iteration MLP.

#define B_  16
#define C_  64
#define H_  256
#define W_  256
#define H2  (H_/2)          // 128
#define W2  (W_/2)          // 128
#define PLANE (H2*W2)       // 16384 elements per output plane
#define NROWS (B_*C_*H2)    // 131072 row-pairs

#define GRID_   608          // 152 SMs * 4 CTAs
#define BLOCK_  256
#define NWARPS  (GRID_*BLOCK_/32)   // 4864

__device__ __forceinline__ void haar2(const float4 t, const float4 u,
                                      float2& A, float2& Hc, float2& V, float2& D)
{
    // t = a0 b0 a1 b1 (top row), u = c0 d0 c1 d1 (bottom row)
    {
        float a = t.x, b = t.y, c = u.x, d = u.y;
        A.x = (a + b + c + d) * 0.5f;  Hc.x = (c + d - a - b) * 0.5f;
        V.x = (b + d - a - c) * 0.5f;  D.x  = (a - b - c + d) * 0.5f;
    }
    {
        float a = t.z, b = t.w, c = u.z, d = u.w;
        A.y = (a + b + c + d) * 0.5f;  Hc.y = (c + d - a - b) * 0.5f;
        V.y = (b + d - a - c) * 0.5f;  D.y  = (a - b - c + d) * 0.5f;
    }
}

__global__ __launch_bounds__(BLOCK_, 4) void dwt_haar_kernel(
    const float* __restrict__ x, float* __restrict__ out)
{
    const int lane = threadIdx.x & 31;
    const int warp0 = (blockIdx.x * BLOCK_ + threadIdx.x) >> 5;

    for (int w = warp0; w < NROWS; w += NWARPS) {
        int h  = w & (H2 - 1);             // output row
        int bc = w >> 7;                   // 0 .. B*C-1 = 1023

        const float4* row0 = reinterpret_cast<const float4*>(
            x + (bc * H_ + 2 * h) * W_);
        const float4* row1 = reinterpret_cast<const float4*>(
            x + (bc * H_ + 2 * h + 1) * W_);

        // 4 independent, fully-coalesced streaming loads (each dense 512B/warp)
        float4 t0 = __ldcs(row0 + lane);
        float4 t1 = __ldcs(row0 + lane + 32);
        float4 u0 = __ldcs(row1 + lane);
        float4 u1 = __ldcs(row1 + lane + 32);

        float2 A0, H0, V0, D0, A1, H1, V1, D1;
        haar2(t0, u0, A0, H0, V0, D0);   // output float2 index: lane
        haar2(t1, u1, A1, H1, V1, D1);   // output float2 index: lane + 32

        float2* o2 = reinterpret_cast<float2*>(out + (bc * 4) * PLANE + h * W2);
        const int pstride = PLANE / 2;   // float2 stride between planes (8192)

        __stcs(o2 + lane,                    A0);
        __stcs(o2 + lane + 32,               A1);
        __stcs(o2 + pstride + lane,          H0);
        __stcs(o2 + pstride + lane + 32,     H1);
        __stcs(o2 + 2 * pstride + lane,      V0);
        __stcs(o2 + 2 * pstride + lane + 32, V1);
        __stcs(o2 + 3 * pstride + lane,      D0);
        __stcs(o2 + 3 * pstride + lane + 32, D1);
    }
}

extern "C" void kernel_launch(void* const* d_in, const int* in_sizes, int n_in,
                              void* d_out, int out_size) {
    const float* x = (const float*)d_in[0];
    float* out = (float*)d_out;
    dwt_haar_kernel<<<GRID_, BLOCK_>>>(x, out);
}

// round 8
// speedup vs baseline: 1.2265x; 1.2265x over previous
#include <cuda_runtime.h>
#include <cuda_bf16.h>

// 2D Haar DWT, single level. (Converged best variant — R3 layout.)
// Input  x  : (B=16, C=64, H=256, W=256) fp32
// Output out: (B, C*4, H/2=128, W/2=128) fp32, planes ordered [cA, cH, cV, cD]
//
// Each thread processes one (bc, h) row position and FOUR output columns:
//   loads 2x float4 from input rows 2h and 2h+1 (4 independent streaming
//   16B loads, 32B inter-thread stride = within coalescing tolerance),
//   writes one float4 to each of the 4 output planes (dense streaming stores).
//
// Measured: 74.6us kernel / ~6.5 TB/s ncu-DRAM, ~7.2 TB/s effective (90% of
// 8 TB/s spec). Wider coarsening (64B stride) and persistent single-wave
// variants both regressed; this is the mixed read/write HBM ceiling.

#define B_  16
#define C_  64
#define H_  256
#define W_  256
#define H2  (H_/2)          // 128
#define W2  (W_/2)          // 128
#define QUADS (W2/4)        // 32 float4-outputs per output row
#define PLANE (H2*W2)       // 16384 elements per output plane

__global__ __launch_bounds__(256) void dwt_haar_kernel(
    const float* __restrict__ x, float* __restrict__ out)
{
    int idx = blockIdx.x * blockDim.x + threadIdx.x;
    // idx in [0, B*C*H2*QUADS) = 16*64*128*32 = 4,194,304
    int wq = idx & (QUADS - 1);            // which group of 4 output cols
    int h  = (idx >> 5) & (H2 - 1);        // output row
    int bc = idx >> 12;                    // 0 .. B*C-1 = 1023

    const float4* row0 = reinterpret_cast<const float4*>(
        x + (bc * H_ + 2 * h) * W_ + wq * 8);
    const float4* row1 = reinterpret_cast<const float4*>(
        x + (bc * H_ + 2 * h + 1) * W_ + wq * 8);

    // 4 independent streaming loads up front (MLP=4)
    float4 t0 = __ldcs(row0);       // a0 b0 a1 b1
    float4 t1 = __ldcs(row0 + 1);   // a2 b2 a3 b3
    float4 u0 = __ldcs(row1);       // c0 d0 c1 d1
    float4 u1 = __ldcs(row1 + 1);   // c2 d2 c3 d3

    float4 cA, cH, cV, cD;
    {
        float a = t0.x, b = t0.y, c = u0.x, d = u0.y;
        cA.x = (a + b + c + d) * 0.5f;
        cH.x = (c + d - a - b) * 0.5f;
        cV.x = (b + d - a - c) * 0.5f;
        cD.x = (a - b - c + d) * 0.5f;
    }
    {
        float a = t0.z, b = t0.w, c = u0.z, d = u0.w;
        cA.y = (a + b + c + d) * 0.5f;
        cH.y = (c + d - a - b) * 0.5f;
        cV.y = (b + d - a - c) * 0.5f;
        cD.y = (a - b - c + d) * 0.5f;
    }
    {
        float a = t1.x, b = t1.y, c = u1.x, d = u1.y;
        cA.z = (a + b + c + d) * 0.5f;
        cH.z = (c + d - a - b) * 0.5f;
        cV.z = (b + d - a - c) * 0.5f;
        cD.z = (a - b - c + d) * 0.5f;
    }
    {
        float a = t1.z, b = t1.w, c = u1.z, d = u1.w;
        cA.w = (a + b + c + d) * 0.5f;
        cH.w = (c + d - a - b) * 0.5f;
        cV.w = (b + d - a - c) * 0.5f;
        cD.w = (a - b - c + d) * 0.5f;
    }

    // output channel = bc*4 + k ; out[(bc*4 + k)*PLANE + h*W2 + 4*wq]
    float4* obase = reinterpret_cast<float4*>(
        out + (bc * 4) * PLANE + h * W2 + 4 * wq);
    const int pstride = PLANE / 4;   // float4 stride between planes
    __stcs(obase,               cA);
    __stcs(obase + pstride,     cH);
    __stcs(obase + 2 * pstride, cV);
    __stcs(obase + 3 * pstride, cD);
}

extern "C" void kernel_launch(void* const* d_in, const int* in_sizes, int n_in,
                              void* d_out, int out_size) {
    const float* x = (const float*)d_in[0];
    float* out = (float*)d_out;
    int total_threads = B_ * C_ * H2 * QUADS;   // 4,194,304
    int block = 256;
    int grid = total_threads / block;           // 16384
    dwt_haar_kernel<<<grid, block>>>(x, out);
}